// round 15
// baseline (speedup 1.0000x reference)
#include <cuda_runtime.h>
#include <cuda_fp16.h>
#include <cstdint>

#define MAXN 100000
#define MAXE 1600000
#define FIN 128
#define FH 64
#define FO 16
#define SCAN_B 1024
#define MAXBLK 128
#define GM_ROWS 128
#define GM_THREADS 256
#define XS_STRIDE 136
#define WS_STRIDE 136
#define GM_SMEM ((GM_ROWS * XS_STRIDE + FH * WS_STRIDE) * 2)  // ~52KB

// Scratch (device globals: allocation-free)
__device__ int                g_is64;
__device__ unsigned long long g_packed[MAXN];   // count<<40 | deg_fixed(2^-24)
__device__ float              g_dinv[MAXN];
__device__ int                g_cnt[MAXN];
__device__ int                g_rowstart[MAXN];
__device__ int                g_cursor[MAXN];
__device__ int                g_blocksum[MAXBLK];
__device__ int2               g_edge[MAXE];     // {src, norm bits}
__device__ __half2            g_h1h[(size_t)MAXN * (FH / 2)];  // fp16 h1 [n][64]
__device__ __half2            g_h2h[(size_t)MAXN * (FO / 2)];  // fp16 h2 [n][16]

__device__ __forceinline__ int edge_src(const void* ei, int E, int e) {
    return g_is64 ? (int)((const long long*)ei)[e] : ((const int*)ei)[e];
}
__device__ __forceinline__ int edge_dst(const void* ei, int E, int e) {
    return g_is64 ? (int)((const long long*)ei)[(size_t)E + e]
                  : ((const int*)ei)[(size_t)E + e];
}

// ---------------------------------------------------------------------------
// init + inline dtype probe (thread 0 of block 0)
// ---------------------------------------------------------------------------
__global__ void init_kernel(const void* ei, int E, int n) {
    int i = blockIdx.x * blockDim.x + threadIdx.x;
    if (i == 0) {
        const long long* p = (const long long*)ei;
        int ok64 = 1;
        int m = E < 64 ? E : 64;
        for (int q = 0; q < m; q++) {
            long long v = p[q];
            long long w = p[(size_t)E + q];
            if (v < 0 || v >= n || w < 0 || w >= n) { ok64 = 0; break; }
        }
        g_is64 = ok64;
    }
    if (i < n) g_packed[i] = (unsigned long long)1 << 24;  // deg = 1.0 fixed
}

// ONE 64-bit atomic per edge
__global__ void cnt_kernel(const void* __restrict__ ei,
                           const float* __restrict__ ew, int E) {
    int e = blockIdx.x * blockDim.x + threadIdx.x;
    if (e >= E) return;
    int d = edge_dst(ei, E, e);
    unsigned long long add =
        ((unsigned long long)1 << 40) +
        (unsigned long long)__float2uint_rn(ew[e] * 16777216.0f);
    atomicAdd(&g_packed[d], add);
}

// ---------------------------------------------------------------------------
// h1 = x @ W1 on tensor cores: mma.sync m16n8k16 f16->f32.
// ---------------------------------------------------------------------------
__global__ void __launch_bounds__(GM_THREADS)
gemm1_kernel(const float* __restrict__ x,
             const float* __restrict__ W1, int n) {
    extern __shared__ __half sm[];
    __half* xs = sm;                          // [128][136]
    __half* ws = sm + GM_ROWS * XS_STRIDE;    // [64][136]
    int t = threadIdx.x;

    for (int i = t; i < FIN * FH / 4; i += GM_THREADS) {
        int k = i / (FH / 4);
        int c = (i % (FH / 4)) * 4;
        float4 w = ((const float4*)W1)[i];
        ws[(c + 0) * WS_STRIDE + k] = __float2half(w.x);
        ws[(c + 1) * WS_STRIDE + k] = __float2half(w.y);
        ws[(c + 2) * WS_STRIDE + k] = __float2half(w.z);
        ws[(c + 3) * WS_STRIDE + k] = __float2half(w.w);
    }

    int rowBase = blockIdx.x * GM_ROWS;
    for (int i = t; i < GM_ROWS * FIN / 4; i += GM_THREADS) {
        int r = i / (FIN / 4), c4 = i % (FIN / 4);
        int row = rowBase + r;
        float4 v = (row < n) ? ((const float4*)(x + (size_t)row * FIN))[c4]
                             : make_float4(0.f, 0.f, 0.f, 0.f);
        __half2* dst = (__half2*)(xs + r * XS_STRIDE + c4 * 4);
        dst[0] = __floats2half2_rn(v.x, v.y);
        dst[1] = __floats2half2_rn(v.z, v.w);
    }
    __syncthreads();

    int warp = t >> 5, lane = t & 31;
    int mw = (warp >> 1) * 32;
    int nw = (warp & 1) * 32;
    int gr = lane >> 2;
    int tg = lane & 3;

    float c[2][4][4];
    #pragma unroll
    for (int i = 0; i < 2; i++)
        #pragma unroll
        for (int j = 0; j < 4; j++)
            #pragma unroll
            for (int q = 0; q < 4; q++) c[i][j][q] = 0.f;

    #pragma unroll
    for (int ks = 0; ks < FIN / 16; ks++) {
        int k0 = ks * 16;
        uint32_t a[2][4];
        #pragma unroll
        for (int mi = 0; mi < 2; mi++) {
            const __half* base = xs + (mw + mi * 16 + gr) * XS_STRIDE + k0 + tg * 2;
            a[mi][0] = *(const uint32_t*)(base);
            a[mi][1] = *(const uint32_t*)(base + 8 * XS_STRIDE);
            a[mi][2] = *(const uint32_t*)(base + 8);
            a[mi][3] = *(const uint32_t*)(base + 8 * XS_STRIDE + 8);
        }
        uint32_t b[4][2];
        #pragma unroll
        for (int ni = 0; ni < 4; ni++) {
            const __half* base = ws + (nw + ni * 8 + gr) * WS_STRIDE + k0 + tg * 2;
            b[ni][0] = *(const uint32_t*)(base);
            b[ni][1] = *(const uint32_t*)(base + 8);
        }
        #pragma unroll
        for (int mi = 0; mi < 2; mi++)
            #pragma unroll
            for (int ni = 0; ni < 4; ni++)
                asm volatile(
                    "mma.sync.aligned.m16n8k16.row.col.f32.f16.f16.f32 "
                    "{%0,%1,%2,%3}, {%4,%5,%6,%7}, {%8,%9}, {%0,%1,%2,%3};"
                    : "+f"(c[mi][ni][0]), "+f"(c[mi][ni][1]),
                      "+f"(c[mi][ni][2]), "+f"(c[mi][ni][3])
                    : "r"(a[mi][0]), "r"(a[mi][1]), "r"(a[mi][2]), "r"(a[mi][3]),
                      "r"(b[ni][0]), "r"(b[ni][1]));
    }

    #pragma unroll
    for (int mi = 0; mi < 2; mi++) {
        #pragma unroll
        for (int ni = 0; ni < 4; ni++) {
            int col2 = (nw + ni * 8 + tg * 2) >> 1;
            int row0 = rowBase + mw + mi * 16 + gr;
            int row1 = row0 + 8;
            if (row0 < n)
                g_h1h[(size_t)row0 * 32 + col2] =
                    __floats2half2_rn(c[mi][ni][0], c[mi][ni][1]);
            if (row1 < n)
                g_h1h[(size_t)row1 * 32 + col2] =
                    __floats2half2_rn(c[mi][ni][2], c[mi][ni][3]);
        }
    }
}

// ---------------------------------------------------------------------------
__global__ void scan1_kernel(int n) {
    __shared__ int s[SCAN_B];
    int t = threadIdx.x;
    int gid = blockIdx.x * SCAN_B + t;
    int v = 0;
    if (gid < n) {
        unsigned long long p = g_packed[gid];
        v = (int)(p >> 40);
        float deg = (float)(p & 0xFFFFFFFFFFull) * (1.0f / 16777216.0f);
        g_dinv[gid] = rsqrtf(deg);
        g_cnt[gid] = v;
    }
    s[t] = v;
    __syncthreads();
    #pragma unroll
    for (int off = 1; off < SCAN_B; off <<= 1) {
        int u = (t >= off) ? s[t - off] : 0;
        __syncthreads();
        s[t] += u;
        __syncthreads();
    }
    if (gid < n) g_rowstart[gid] = s[t] - v;
    if (t == SCAN_B - 1) g_blocksum[blockIdx.x] = s[t];
}

__global__ void scan2_kernel(int nb) {
    __shared__ int s[MAXBLK];
    int t = threadIdx.x;
    int v = (t < nb) ? g_blocksum[t] : 0;
    s[t] = v;
    __syncthreads();
    #pragma unroll
    for (int off = 1; off < MAXBLK; off <<= 1) {
        int u = (t >= off) ? s[t - off] : 0;
        __syncthreads();
        s[t] += u;
        __syncthreads();
    }
    if (t < nb) g_blocksum[t] = s[t] - v;
}

__global__ void scan3_kernel(int n) {
    int gid = blockIdx.x * blockDim.x + threadIdx.x;
    if (gid >= n) return;
    int r = g_rowstart[gid] + g_blocksum[gid >> 10];
    g_rowstart[gid] = r;
    g_cursor[gid] = r;
}

__global__ void build_kernel(const void* __restrict__ ei,
                             const float* __restrict__ ew, int E) {
    int e = blockIdx.x * blockDim.x + threadIdx.x;
    if (e >= E) return;
    int s = edge_src(ei, E, e);
    int d = edge_dst(ei, E, e);
    int pos = atomicAdd(&g_cursor[d], 1);
    float nm = g_dinv[s] * ew[e] * g_dinv[d];
    g_edge[pos] = make_int2(s, __float_as_int(nm));
}

// ---------------------------------------------------------------------------
// agg1 + gemm2 fused. 256 threads = 8 warps = 8 nodes per block.
// Phase 1 (warp per node): z = relu(agg + self + b1), staged in smem.
// Phase 2 (128 threads): h2[node][f] = sum_k z[k] * W2[k][f], fp16 store.
// ---------------------------------------------------------------------------
__global__ void agg1_kernel(const float* __restrict__ b1,
                            const float* __restrict__ W2, int n) {
    __shared__ float zs[8][FH];       // 2 KB
    __shared__ float sW2[FH * FO];    // 4 KB
    __shared__ float sb1[FH];

    int t = threadIdx.x;
    for (int i = t; i < FH * FO; i += 256) sW2[i] = W2[i];
    if (t < FH) sb1[t] = b1[t];

    int wi = t >> 5;                  // warp in block: 0..7
    int lane = t & 31;
    int node = blockIdx.x * 8 + wi;
    bool valid = node < n;

    if (valid) {
        const __half2* h1 = g_h1h;
        int start = g_rowstart[node];
        int end = start + g_cnt[node];
        float2 acc = make_float2(0.f, 0.f);

        int j = start;
        for (; j + 8 <= end; j += 8) {
            int2 e0 = g_edge[j],   e1 = g_edge[j+1], e2 = g_edge[j+2], e3 = g_edge[j+3];
            int2 e4 = g_edge[j+4], e5 = g_edge[j+5], e6 = g_edge[j+6], e7 = g_edge[j+7];
            float2 v0 = __half22float2(h1[(size_t)e0.x * 32 + lane]);
            float2 v1 = __half22float2(h1[(size_t)e1.x * 32 + lane]);
            float2 v2 = __half22float2(h1[(size_t)e2.x * 32 + lane]);
            float2 v3 = __half22float2(h1[(size_t)e3.x * 32 + lane]);
            float2 v4 = __half22float2(h1[(size_t)e4.x * 32 + lane]);
            float2 v5 = __half22float2(h1[(size_t)e5.x * 32 + lane]);
            float2 v6 = __half22float2(h1[(size_t)e6.x * 32 + lane]);
            float2 v7 = __half22float2(h1[(size_t)e7.x * 32 + lane]);
            float n0 = __int_as_float(e0.y), n1 = __int_as_float(e1.y);
            float n2 = __int_as_float(e2.y), n3 = __int_as_float(e3.y);
            float n4 = __int_as_float(e4.y), n5 = __int_as_float(e5.y);
            float n6 = __int_as_float(e6.y), n7 = __int_as_float(e7.y);
            acc.x += n0 * v0.x + n1 * v1.x + n2 * v2.x + n3 * v3.x
                   + n4 * v4.x + n5 * v5.x + n6 * v6.x + n7 * v7.x;
            acc.y += n0 * v0.y + n1 * v1.y + n2 * v2.y + n3 * v3.y
                   + n4 * v4.y + n5 * v5.y + n6 * v6.y + n7 * v7.y;
        }
        for (; j < end; j++) {
            int2 e = g_edge[j];
            float nm = __int_as_float(e.y);
            float2 v = __half22float2(h1[(size_t)e.x * 32 + lane]);
            acc.x += nm * v.x;
            acc.y += nm * v.y;
        }
        float dv = g_dinv[node];
        float self = dv * dv;
        float2 hs = __half22float2(h1[(size_t)node * 32 + lane]);
        acc.x += self * hs.x;
        acc.y += self * hs.y;
        zs[wi][lane * 2 + 0] = fmaxf(acc.x + sb1[lane * 2 + 0], 0.f);
        zs[wi][lane * 2 + 1] = fmaxf(acc.y + sb1[lane * 2 + 1], 0.f);
    }
    __syncthreads();

    // Phase 2: 128 threads -> one (node, f) each
    if (t < 128) {
        int ln = t >> 4;              // local node 0..7
        int f = t & 15;
        int gnode = blockIdx.x * 8 + ln;
        if (gnode < n) {
            float acc = 0.f;
            #pragma unroll
            for (int k = 0; k < FH; k++)
                acc += zs[ln][k] * sW2[k * FO + f];
            ((__half*)g_h2h)[(size_t)gnode * FO + f] = __float2half(acc);
        }
    }
}

// ---------------------------------------------------------------------------
__global__ void agg2_kernel(const float* __restrict__ b2,
                            float* __restrict__ out, int n) {
    int gid = blockIdx.x * blockDim.x + threadIdx.x;
    int node = gid >> 4;
    bool live = node < n;
    if (!live) node = 0;
    int f = gid & 15;
    const __half* h2 = (const __half*)g_h2h;
    int start = g_rowstart[node];
    int end = start + g_cnt[node];
    float acc = 0.f;

    int j = start;
    for (; j + 4 <= end; j += 4) {
        int2 e0 = g_edge[j],   e1 = g_edge[j+1];
        int2 e2 = g_edge[j+2], e3 = g_edge[j+3];
        acc += __int_as_float(e0.y) * __half2float(h2[(size_t)e0.x * FO + f])
             + __int_as_float(e1.y) * __half2float(h2[(size_t)e1.x * FO + f])
             + __int_as_float(e2.y) * __half2float(h2[(size_t)e2.x * FO + f])
             + __int_as_float(e3.y) * __half2float(h2[(size_t)e3.x * FO + f]);
    }
    for (; j < end; j++) {
        int2 e = g_edge[j];
        acc += __int_as_float(e.y) * __half2float(h2[(size_t)e.x * FO + f]);
    }
    float dv = g_dinv[node];
    acc += dv * dv * __half2float(h2[(size_t)node * FO + f]) + b2[f];

    float m = acc;
    #pragma unroll
    for (int off = 8; off > 0; off >>= 1)
        m = fmaxf(m, __shfl_xor_sync(0xffffffffu, m, off));
    float e = expf(acc - m);
    float ssum = e;
    #pragma unroll
    for (int off = 8; off > 0; off >>= 1)
        ssum += __shfl_xor_sync(0xffffffffu, ssum, off);
    if (live) out[(size_t)node * FO + f] = acc - m - logf(ssum);
}

// ---------------------------------------------------------------------------
extern "C" void kernel_launch(void* const* d_in, const int* in_sizes, int n_in,
                              void* d_out, int out_size) {
    const float* x  = (const float*)d_in[0];
    const void*  ei = d_in[1];
    const float* ew = (const float*)d_in[2];
    const float* W1 = (const float*)d_in[3];
    const float* b1 = (const float*)d_in[4];
    const float* W2 = (const float*)d_in[5];
    const float* b2 = (const float*)d_in[6];
    float*       out = (float*)d_out;

    int n = in_sizes[0] / FIN;
    int E = in_sizes[2];

    static cudaStream_t s1 = nullptr;
    static cudaEvent_t evFork = nullptr, evJoin = nullptr;
    static bool inited = false;
    if (!inited) {
        cudaStreamCreateWithFlags(&s1, cudaStreamNonBlocking);
        cudaEventCreateWithFlags(&evFork, cudaEventDisableTiming);
        cudaEventCreateWithFlags(&evJoin, cudaEventDisableTiming);
        cudaFuncSetAttribute(gemm1_kernel,
                             cudaFuncAttributeMaxDynamicSharedMemorySize, GM_SMEM);
        inited = true;
    }

    // fork FIRST: gemm1 overlaps the entire CSR chain
    cudaEventRecord(evFork, 0);
    cudaStreamWaitEvent(s1, evFork, 0);
    gemm1_kernel<<<(n + GM_ROWS - 1) / GM_ROWS, GM_THREADS, GM_SMEM, s1>>>(x, W1, n);
    cudaEventRecord(evJoin, s1);

    // main stream: CSR chain (init includes dtype probe)
    init_kernel<<<(n + 255) / 256, 256>>>(ei, E, n);
    cnt_kernel<<<(E + 255) / 256, 256>>>(ei, ew, E);

    int nb = (n + SCAN_B - 1) / SCAN_B;
    scan1_kernel<<<nb, SCAN_B>>>(n);
    scan2_kernel<<<1, MAXBLK>>>(nb);
    scan3_kernel<<<(n + 255) / 256, 256>>>(n);

    build_kernel<<<(E + 255) / 256, 256>>>(ei, ew, E);

    // join: agg1 needs h1 (side stream) and CSR (main stream)
    cudaStreamWaitEvent(0, evJoin, 0);

    agg1_kernel<<<(n + 7) / 8, 256>>>(b1, W2, n);

    long long t2 = (long long)n * 16;
    agg2_kernel<<<(int)((t2 + 255) / 256), 256>>>(b2, out, n);
}